// round 1
// baseline (speedup 1.0000x reference)
#include <cuda_runtime.h>
#include <math.h>

#define B   128
#define T   128
#define E   512
#define H   384
#define FH  1536   // 4*H
#define Z   128
#define ZH  256
#define NSTEP 127

// ---------------- device scratch (static allocation: allowed) ----------------
__device__ float g_G0[NSTEP * FH * B];     // ~100 MB: precomputed x@Wih0^T, layout [t][j][b]
__device__ float g_h0[2][H * B];           // ping-pong, layout [feature][batch]
__device__ float g_h1[2][H * B];
__device__ float g_c0[H * B];
__device__ float g_c1[H * B];
__device__ int   g_act[NSTEP];
__device__ unsigned g_count;               // barrier arrivals
__device__ volatile unsigned g_gen;        // barrier generation

// ---------------- helpers ----------------
__device__ __forceinline__ float sigf(float x) { return 1.0f / (1.0f + expf(-x)); }

__device__ __forceinline__ void grid_sync() {
    __syncthreads();
    if (threadIdx.x == 0) {
        unsigned my = g_gen;
        __threadfence();
        unsigned arrived = atomicAdd(&g_count, 1u);
        if (arrived == gridDim.x - 1) {
            g_count = 0;
            __threadfence();
            g_gen = my + 1;
        } else {
            while (g_gen == my) { }
        }
        __threadfence();
    }
    __syncthreads();
}

// ---------------- sticky active flags ----------------
__global__ void act_kernel(const int* __restrict__ seq) {
    __shared__ int nz[NSTEP];
    int t = threadIdx.x;
    if (t < NSTEP) {
        int s = 0;
        for (int b = 0; b < B; b++) s += seq[b * T + t + 1];
        nz[t] = (s != 0);
    }
    __syncthreads();
    if (t == 0) {
        int a = 1;
        for (int i = 0; i < NSTEP; i++) { a = a && nz[i]; g_act[i] = a; }
    }
}

// ---------------- precompute G0[t][j][b] = sum_k embed[seq[b][t+1]][k] * Wih0[j][k] ----------------
__global__ __launch_bounds__(256) void pre_kernel(const int* __restrict__ seq,
                                                  const float* __restrict__ embed,
                                                  const float* __restrict__ Wih0) {
    const int t = blockIdx.y;              // 0..126
    const int jbase = blockIdx.x * 64;     // 24 tiles of 64 cols
    __shared__ int   s_idx[B];
    __shared__ float s_x[B][17];
    __shared__ float s_w[64][17];
    const int tid = threadIdx.x;
    if (tid < B) s_idx[tid] = seq[tid * T + t + 1];
    __syncthreads();

    const int tb = tid & 15;       // b-lane within group of 16
    const int tjj = tid >> 4;      // 0..15: j group of 4
    float acc[8][4];
#pragma unroll
    for (int u = 0; u < 8; u++)
#pragma unroll
        for (int v = 0; v < 4; v++) acc[u][v] = 0.0f;

    for (int kc = 0; kc < E; kc += 16) {
        for (int i = tid; i < B * 16; i += 256) {
            int b = i >> 4, k = i & 15;
            s_x[b][k] = embed[s_idx[b] * E + kc + k];
        }
        for (int i = tid; i < 64 * 16; i += 256) {
            int j = i >> 4, k = i & 15;
            s_w[j][k] = Wih0[(jbase + j) * E + kc + k];
        }
        __syncthreads();
#pragma unroll
        for (int k = 0; k < 16; k++) {
            float xv[8], wv[4];
#pragma unroll
            for (int u = 0; u < 8; u++) xv[u] = s_x[u * 16 + tb][k];
#pragma unroll
            for (int v = 0; v < 4; v++) wv[v] = s_w[tjj * 4 + v][k];
#pragma unroll
            for (int u = 0; u < 8; u++)
#pragma unroll
                for (int v = 0; v < 4; v++) acc[u][v] = fmaf(xv[u], wv[v], acc[u][v]);
        }
        __syncthreads();
    }
#pragma unroll
    for (int v = 0; v < 4; v++) {
        int j = jbase + tjj * 4 + v;
        float* dst = g_G0 + ((size_t)t * FH + j) * B;
#pragma unroll
        for (int u = 0; u < 8; u++) dst[u * 16 + tb] = acc[u][v];
    }
}

// ---------------- persistent recurrent kernel + VAE head ----------------
// grid = 128 CTAs (all resident), 384 threads = 12 warps = 3 h-features x 4 gates.
__global__ __launch_bounds__(384, 1) void rnn_kernel(
    const float* __restrict__ Whh0, const float* __restrict__ Wih1,
    const float* __restrict__ Whh1, const float* __restrict__ eps,
    const float* __restrict__ W1,   const float* __restrict__ bias1,
    const float* __restrict__ Wmu,  const float* __restrict__ bmu,
    const float* __restrict__ Wlv,  const float* __restrict__ blv,
    float* __restrict__ out) {
    __shared__ float s_h[64][128];        // staged h chunk [k][b]
    __shared__ float s_g[4][3][128];      // gate exchange [gate][hfi][b]
    __shared__ float s_hb[H];             // head: h1 column for this batch row
    __shared__ float s_hv[ZH];

    const int tid  = threadIdx.x;
    const int lane = tid & 31;
    const int w    = tid >> 5;
    const int hfi  = w >> 2;              // 0..2
    const int gate = w & 3;               // 0=i 1=f 2=g 3=o
    const int hf   = blockIdx.x * 3 + hfi;
    const int j0   = gate * H + hf;       // GEMM row in [0,1536)

    // zero-init state (every launch / graph replay)
    {
        int idx = (blockIdx.x * 3 + (tid >> 7)) * B + (tid & 127);
        g_h0[0][idx] = 0.0f; g_h1[0][idx] = 0.0f;
        g_c0[idx] = 0.0f;    g_c1[idx] = 0.0f;
    }
    __threadfence();
    grid_sync();

    int p = 0;
    for (int t = 0; t < NSTEP; t++) {
        if (!g_act[t]) break;
        const float* h0r = g_h0[p];
        float*       h0w = g_h0[p ^ 1];
        const float* h1r = g_h1[p];
        float*       h1w = g_h1[p ^ 1];

        // ---- pass0: gates0 = G0[t] + h0r @ Whh0^T  (K=384)
        float4 acc = *(const float4*)(g_G0 + ((size_t)t * FH + j0) * B + lane * 4);
        {
            const float* wr = Whh0 + j0 * H;
            for (int c = 0; c < 6; c++) {
                const float4* src = (const float4*)(h0r + c * 64 * B);
                float4* dst = (float4*)&s_h[0][0];
                for (int i = tid; i < 64 * B / 4; i += 384) dst[i] = __ldcg(src + i);
                __syncthreads();
#pragma unroll
                for (int k = 0; k < 64; k++) {
                    float wv = __ldg(wr + c * 64 + k);
                    float4 h4 = *(const float4*)&s_h[k][lane * 4];
                    acc.x = fmaf(h4.x, wv, acc.x);
                    acc.y = fmaf(h4.y, wv, acc.y);
                    acc.z = fmaf(h4.z, wv, acc.z);
                    acc.w = fmaf(h4.w, wv, acc.w);
                }
                __syncthreads();
            }
        }
        *(float4*)&s_g[gate][hfi][lane * 4] = acc;
        __syncthreads();
        {
            int ehf = tid >> 7, b = tid & 127;
            float ig = s_g[0][ehf][b], fg = s_g[1][ehf][b];
            float gv = s_g[2][ehf][b], og = s_g[3][ehf][b];
            int idx = (blockIdx.x * 3 + ehf) * B + b;
            float c0 = g_c0[idx];
            float nc = sigf(fg) * c0 + sigf(ig) * tanhf(gv);
            float nh = sigf(og) * tanhf(nc);
            g_c0[idx] = nc;
            h0w[idx]  = nh;
        }
        __threadfence();
        grid_sync();

        // ---- pass1: gates1 = h0w @ Wih1^T + h1r @ Whh1^T  (K=768)
        float4 acc1 = make_float4(0.f, 0.f, 0.f, 0.f);
        {
            const float* wr1 = Wih1 + j0 * H;
            const float* wr2 = Whh1 + j0 * H;
            for (int c = 0; c < 12; c++) {
                const int cc = (c < 6) ? c : c - 6;
                const float4* src = (const float4*)(((c < 6) ? h0w : h1r) + cc * 64 * B);
                const float*  wr  = ((c < 6) ? wr1 : wr2) + cc * 64;
                float4* dst = (float4*)&s_h[0][0];
                for (int i = tid; i < 64 * B / 4; i += 384) dst[i] = __ldcg(src + i);
                __syncthreads();
#pragma unroll
                for (int k = 0; k < 64; k++) {
                    float wv = __ldg(wr + k);
                    float4 h4 = *(const float4*)&s_h[k][lane * 4];
                    acc1.x = fmaf(h4.x, wv, acc1.x);
                    acc1.y = fmaf(h4.y, wv, acc1.y);
                    acc1.z = fmaf(h4.z, wv, acc1.z);
                    acc1.w = fmaf(h4.w, wv, acc1.w);
                }
                __syncthreads();
            }
        }
        *(float4*)&s_g[gate][hfi][lane * 4] = acc1;
        __syncthreads();
        {
            int ehf = tid >> 7, b = tid & 127;
            float ig = s_g[0][ehf][b], fg = s_g[1][ehf][b];
            float gv = s_g[2][ehf][b], og = s_g[3][ehf][b];
            int idx = (blockIdx.x * 3 + ehf) * B + b;
            float c1 = g_c1[idx];
            float nc = sigf(fg) * c1 + sigf(ig) * tanhf(gv);
            float nh = sigf(og) * tanhf(nc);
            g_c1[idx] = nc;
            h1w[idx]  = nh;   // h1 == rnn "out"
        }
        __threadfence();
        grid_sync();
        p ^= 1;
    }

    // ---- VAE head: this CTA handles batch row b = blockIdx.x
    const int b = blockIdx.x;
    const float* h1f = g_h1[p];
    if (tid < H) s_hb[tid] = __ldcg(h1f + tid * B + b);
    __syncthreads();
    if (tid < ZH) {
        float a = bias1[tid];
        const float* wr = W1 + tid * H;
#pragma unroll 4
        for (int k = 0; k < H; k++) a = fmaf(s_hb[k], __ldg(wr + k), a);
        s_hv[tid] = fmaxf(a, 0.0f);
    }
    __syncthreads();
    if (tid < Z) {
        float mu = bmu[tid], lv = blv[tid];
        const float* wmu = Wmu + tid * ZH;
        const float* wlv = Wlv + tid * ZH;
#pragma unroll 4
        for (int k = 0; k < ZH; k++) {
            float hk = s_hv[k];
            mu = fmaf(hk, __ldg(wmu + k), mu);
            lv = fmaf(hk, __ldg(wlv + k), lv);
        }
        float zz = mu + eps[b * Z + tid] * expf(0.5f * lv);
        out[b * Z + tid] = mu;                           // z_mu
        out[B * Z + b * Z + tid] = lv;                   // z_logvar
        out[2 * B * Z + b * (H + Z) + H + tid] = zz;     // concat[:, H:]
    }
    if (tid < H) out[2 * B * Z + b * (H + Z) + tid] = s_hb[tid];  // concat[:, :H]
}

// ---------------- launch ----------------
extern "C" void kernel_launch(void* const* d_in, const int* in_sizes, int n_in,
                              void* d_out, int out_size) {
    const int*   seq   = (const int*)d_in[0];
    const float* eps   = (const float*)d_in[1];
    const float* embed = (const float*)d_in[2];
    const float* Wih0  = (const float*)d_in[3];
    const float* Whh0  = (const float*)d_in[4];
    const float* Wih1  = (const float*)d_in[5];
    const float* Whh1  = (const float*)d_in[6];
    const float* W1    = (const float*)d_in[7];
    const float* b1    = (const float*)d_in[8];
    const float* Wmu   = (const float*)d_in[9];
    const float* bmu   = (const float*)d_in[10];
    const float* Wlv   = (const float*)d_in[11];
    const float* blv   = (const float*)d_in[12];
    float* out = (float*)d_out;

    act_kernel<<<1, 128>>>(seq);
    pre_kernel<<<dim3(24, 127), 256>>>(seq, embed, Wih0);
    rnn_kernel<<<128, 384>>>(Whh0, Wih1, Whh1, eps, W1, b1, Wmu, bmu, Wlv, blv, out);
}

// round 3
// speedup vs baseline: 3.4259x; 3.4259x over previous
#include <cuda_runtime.h>
#include <math.h>

#define B   128
#define T   128
#define E   512
#define H   384
#define FH  1536
#define Z   128
#define ZH  256
#define NSTEP 127

typedef unsigned long long ull;

// ---------------- device scratch ----------------
__device__ float g_G0[NSTEP * FH * B];     // precomputed x@Wih0^T, layout [t][j][b]
__device__ float g_h0[2][H * B];           // ping-pong, layout [feature][batch]
__device__ float g_h1[2][H * B];
__device__ int   g_act[NSTEP];
__device__ __align__(16) int g_slot[128];  // barrier arrival slots (monotonic epochs)
__device__ int   g_release;                // barrier release epoch (monotonic across replays)

// ---------------- helpers ----------------
__device__ __forceinline__ ull ffma2(ull a, ull b, ull c) {
    ull d; asm("fma.rn.f32x2 %0,%1,%2,%3;" : "=l"(d) : "l"(a), "l"(b), "l"(c)); return d;
}
__device__ __forceinline__ ull pack2(float x, float y) {
    ull r; asm("mov.b64 %0,{%1,%2};" : "=l"(r) : "f"(x), "f"(y)); return r;
}
__device__ __forceinline__ float sigf(float x) { return __fdividef(1.0f, 1.0f + __expf(-x)); }

// one grid barrier: parallel flag arrivals + CTA0 aggregates + release broadcast.
__device__ __forceinline__ void gsync(int epoch) {
    __threadfence();
    __syncthreads();
    if (threadIdx.x == 0) *((volatile int*)&g_slot[blockIdx.x]) = epoch;
    if (blockIdx.x == 0 && threadIdx.x < 32) {
        const volatile int* sp = g_slot;
        int i0 = threadIdx.x * 4;
        for (;;) {
            int a = sp[i0], b = sp[i0 + 1], c = sp[i0 + 2], d = sp[i0 + 3];
            bool ok = (a - epoch) >= 0 && (b - epoch) >= 0 && (c - epoch) >= 0 && (d - epoch) >= 0;
            if (__all_sync(0xffffffffu, ok)) break;
        }
        if (threadIdx.x == 0) *((volatile int*)&g_release) = epoch;
    }
    if (threadIdx.x == 0) { while ((*((volatile int*)&g_release) - epoch) < 0) {} }
    __syncthreads();
}

// ---------------- sticky active flags ----------------
__global__ void act_kernel(const int* __restrict__ seq) {
    __shared__ int nz[NSTEP];
    int t = threadIdx.x;
    if (t < NSTEP) {
        int s = 0;
        for (int b = 0; b < B; b++) s += seq[b * T + t + 1];
        nz[t] = (s != 0);
    }
    __syncthreads();
    if (t == 0) {
        int a = 1;
        for (int i = 0; i < NSTEP; i++) { a = a && nz[i]; g_act[i] = a; }
    }
}

// ---------------- precompute G0[t][j][b], 128x128 tile, f32x2 ----------------
__global__ __launch_bounds__(256) void pre_kernel(const int* __restrict__ seq,
                                                  const float* __restrict__ embed,
                                                  const float* __restrict__ Wih0) {
    const int t  = blockIdx.y;
    const int jb = blockIdx.x * 128;
    __shared__ int   s_idx[B];
    __shared__ float s_x[32 * 128];   // [k][b]
    __shared__ float s_w[32 * 128];   // [k][j]
    const int tid = threadIdx.x;
    if (tid < B) s_idx[tid] = seq[tid * T + t + 1];
    __syncthreads();

    const int col = tid & 127;          // staging column (b or j)
    const int kg  = tid >> 7;           // 0/1 : k half
    const int jt  = (tid >> 4) * 8;     // 0..120
    const int bt  = (tid & 15) * 8;     // 0..120

    ull acc[8][4];
#pragma unroll
    for (int u = 0; u < 8; u++)
#pragma unroll
        for (int v = 0; v < 4; v++) acc[u][v] = 0ull;

    const float* xrow0 = embed + (size_t)s_idx[col] * E;
    const float* wrow0 = Wih0 + (size_t)(jb + col) * E;

    for (int kc = 0; kc < E; kc += 32) {
        // stage (k-major, conflict-free STS)
#pragma unroll
        for (int q = 0; q < 4; q++) {
            float4 xv = __ldg((const float4*)(xrow0 + kc + kg * 16) + q);
            float4 wv = __ldg((const float4*)(wrow0 + kc + kg * 16) + q);
            int k0 = kg * 16 + q * 4;
            s_x[(k0 + 0) * 128 + col] = xv.x; s_x[(k0 + 1) * 128 + col] = xv.y;
            s_x[(k0 + 2) * 128 + col] = xv.z; s_x[(k0 + 3) * 128 + col] = xv.w;
            s_w[(k0 + 0) * 128 + col] = wv.x; s_w[(k0 + 1) * 128 + col] = wv.y;
            s_w[(k0 + 2) * 128 + col] = wv.z; s_w[(k0 + 3) * 128 + col] = wv.w;
        }
        __syncthreads();
#pragma unroll 4
        for (int k = 0; k < 32; k++) {
            const float4* xb = (const float4*)(s_x + k * 128 + bt);
            float4 x0 = xb[0], x1 = xb[1];
            ull xp0 = pack2(x0.x, x0.y), xp1 = pack2(x0.z, x0.w);
            ull xp2 = pack2(x1.x, x1.y), xp3 = pack2(x1.z, x1.w);
            const float4* wb = (const float4*)(s_w + k * 128 + jt);
            float4 w0 = wb[0], w1 = wb[1];
            float wf[8] = {w0.x, w0.y, w0.z, w0.w, w1.x, w1.y, w1.z, w1.w};
#pragma unroll
            for (int u = 0; u < 8; u++) {
                ull wp = pack2(wf[u], wf[u]);
                acc[u][0] = ffma2(xp0, wp, acc[u][0]);
                acc[u][1] = ffma2(xp1, wp, acc[u][1]);
                acc[u][2] = ffma2(xp2, wp, acc[u][2]);
                acc[u][3] = ffma2(xp3, wp, acc[u][3]);
            }
        }
        __syncthreads();
    }
#pragma unroll
    for (int u = 0; u < 8; u++) {
        ull* dst = (ull*)(g_G0 + ((size_t)t * FH + jb + jt + u) * B + bt);
        dst[0] = acc[u][0]; dst[1] = acc[u][1]; dst[2] = acc[u][2]; dst[3] = acc[u][3];
    }
}

// ---------------- persistent recurrent kernel + VAE head ----------------
// 128 CTAs x 384 threads. CTA bx owns 12 gate-rows {g*H + 3bx + hf}.
// Warps split K; each warp LDGs h[k][:] once and reuses it vs all 12 rows.
extern __shared__ char dynsmem[];

__global__ __launch_bounds__(384, 1) void rnn_kernel(
    const float* __restrict__ Whh0, const float* __restrict__ Wih1,
    const float* __restrict__ Whh1, const float* __restrict__ eps,
    const float* __restrict__ W1,   const float* __restrict__ bias1,
    const float* __restrict__ Wmu,  const float* __restrict__ bmu,
    const float* __restrict__ Wlv,  const float* __restrict__ blv,
    float* __restrict__ out) {

    float2* sW0  = (float2*)dynsmem;                       // [384][12] dup pairs
    float2* sW1  = (float2*)(dynsmem + 36864);             // [768][12] dup pairs
    float*  sRed = (float*)(dynsmem + 36864 + 73728);      // [12 warps][12 rows][128 b]

    const int tid  = threadIdx.x;
    const int lane = tid & 31;
    const int w    = tid >> 5;
    const int bx   = blockIdx.x;

    // persistent weights, duplicated as (w,w) for f32x2
    for (int i = tid; i < 384 * 12; i += 384) {
        int k = i / 12, lr = i % 12;
        int g = lr / 3, hf = lr % 3;
        float v = Whh0[(g * H + bx * 3 + hf) * H + k];
        sW0[i] = make_float2(v, v);
    }
    for (int i = tid; i < 768 * 12; i += 384) {
        int k = i / 12, lr = i % 12;
        int g = lr / 3, hf = lr % 3;
        int j = g * H + bx * 3 + hf;
        float v = (k < 384) ? Wih1[j * H + k] : Whh1[j * H + (k - 384)];
        sW1[i] = make_float2(v, v);
    }
    // zero-init this CTA's h features
    {
        int idx = bx * 3 * B + tid;     // 384 = 3*B
        g_h0[0][idx] = 0.0f;
        g_h1[0][idx] = 0.0f;
    }
    // epilogue thread role + register cell state
    const int hf_e = tid >> 7;      // 0..2
    const int b_e  = tid & 127;
    float c0r = 0.0f, c1r = 0.0f;

    const int ebase = *((volatile int*)&g_release);   // replay-safe monotonic base
    int epoch = ebase;
    gsync(++epoch);

    int p = 0;
    int t;
    for (t = 0; t < NSTEP; t++) {
        if (!g_act[t]) break;
        const float* h0r = g_h0[p];
        float*       h0w = g_h0[p ^ 1];
        const float* h1r = g_h1[p];
        float*       h1w = g_h1[p ^ 1];

        // ---- pass0 inner: rows x h0r, K=384 (32 k per warp)
        ull acc[12][2];
#pragma unroll
        for (int lr = 0; lr < 12; lr++) { acc[lr][0] = 0ull; acc[lr][1] = 0ull; }
        {
            const int k0 = w * 32;
#pragma unroll 4
            for (int kk = 0; kk < 32; kk++) {
                int k = k0 + kk;
                float4 h4 = __ldcg((const float4*)(h0r + k * B) + lane);
                ull hlo = pack2(h4.x, h4.y), hhi = pack2(h4.z, h4.w);
                const ulonglong2* wb = (const ulonglong2*)(sW0 + k * 12);
#pragma unroll
                for (int q = 0; q < 6; q++) {
                    ulonglong2 ww = wb[q];
                    acc[2 * q][0]     = ffma2(hlo, ww.x, acc[2 * q][0]);
                    acc[2 * q][1]     = ffma2(hhi, ww.x, acc[2 * q][1]);
                    acc[2 * q + 1][0] = ffma2(hlo, ww.y, acc[2 * q + 1][0]);
                    acc[2 * q + 1][1] = ffma2(hhi, ww.y, acc[2 * q + 1][1]);
                }
            }
        }
#pragma unroll
        for (int lr = 0; lr < 12; lr++) {
            ull* d = (ull*)(sRed + (w * 12 + lr) * B + 4 * lane);
            d[0] = acc[lr][0]; d[1] = acc[lr][1];
        }
        __syncthreads();
        // ---- epilogue 0: gate combine + cell update
        {
            float gv[4];
#pragma unroll
            for (int g = 0; g < 4; g++) {
                int lr = g * 3 + hf_e;
                float s = __ldcs(g_G0 + ((size_t)t * FH + g * H + bx * 3 + hf_e) * B + b_e);
#pragma unroll
                for (int ww2 = 0; ww2 < 12; ww2++) s += sRed[(ww2 * 12 + lr) * B + b_e];
                gv[g] = s;
            }
            float nc = sigf(gv[1]) * c0r + sigf(gv[0]) * tanhf(gv[2]);
            c0r = nc;
            float nh = sigf(gv[3]) * tanhf(nc);
            __stcg(h0w + (bx * 3 + hf_e) * B + b_e, nh);
        }
        gsync(++epoch);

        // ---- pass1 inner: rows x [h0w | h1r], K=768 (64 k per warp, no straddle)
#pragma unroll
        for (int lr = 0; lr < 12; lr++) { acc[lr][0] = 0ull; acc[lr][1] = 0ull; }
        {
            const float* src   = (w < 6) ? h0w : h1r;
            const int    fbase = (w < 6) ? w * 64 : (w - 6) * 64;
            const int    k0    = w * 64;
#pragma unroll 4
            for (int kk = 0; kk < 64; kk++) {
                float4 h4 = __ldcg((const float4*)(src + (fbase + kk) * B) + lane);
                ull hlo = pack2(h4.x, h4.y), hhi = pack2(h4.z, h4.w);
                const ulonglong2* wb = (const ulonglong2*)(sW1 + (k0 + kk) * 12);
#pragma unroll
                for (int q = 0; q < 6; q++) {
                    ulonglong2 ww = wb[q];
                    acc[2 * q][0]     = ffma2(hlo, ww.x, acc[2 * q][0]);
                    acc[2 * q][1]     = ffma2(hhi, ww.x, acc[2 * q][1]);
                    acc[2 * q + 1][0] = ffma2(hlo, ww.y, acc[2 * q + 1][0]);
                    acc[2 * q + 1][1] = ffma2(hhi, ww.y, acc[2 * q + 1][1]);
                }
            }
        }
#pragma unroll
        for (int lr = 0; lr < 12; lr++) {
            ull* d = (ull*)(sRed + (w * 12 + lr) * B + 4 * lane);
            d[0] = acc[lr][0]; d[1] = acc[lr][1];
        }
        __syncthreads();
        // ---- epilogue 1
        {
            float gv[4];
#pragma unroll
            for (int g = 0; g < 4; g++) {
                int lr = g * 3 + hf_e;
                float s = 0.0f;
#pragma unroll
                for (int ww2 = 0; ww2 < 12; ww2++) s += sRed[(ww2 * 12 + lr) * B + b_e];
                gv[g] = s;
            }
            float nc = sigf(gv[1]) * c1r + sigf(gv[0]) * tanhf(gv[2]);
            c1r = nc;
            float nh = sigf(gv[3]) * tanhf(nc);
            __stcg(h1w + (bx * 3 + hf_e) * B + b_e, nh);
        }
        __syncthreads();   // protect sRed before next step's partial stores
        p ^= 1;
    }

    // ---- FINAL grid barrier: head reads h1 features written by ALL CTAs.
    gsync(++epoch);

    // ---- VAE head: CTA bx handles batch row b = bx
    float* s_hb = sRed;            // reuse
    float* s_hv = sRed + 512;
    const float* h1f = g_h1[p];
    const int b = bx;
    s_hb[tid] = __ldcg(h1f + tid * B + b);   // tid < 384 == H
    __syncthreads();
    if (tid < ZH) {
        float a = bias1[tid];
        const float* wr = W1 + tid * H;
#pragma unroll 4
        for (int k = 0; k < H; k++) a = fmaf(s_hb[k], __ldg(wr + k), a);
        s_hv[tid] = fmaxf(a, 0.0f);
    }
    __syncthreads();
    if (tid < Z) {
        float mu = bmu[tid], lv = blv[tid];
        const float* wmu = Wmu + tid * ZH;
        const float* wlv = Wlv + tid * ZH;
#pragma unroll 4
        for (int k = 0; k < ZH; k++) {
            float hk = s_hv[k];
            mu = fmaf(hk, __ldg(wmu + k), mu);
            lv = fmaf(hk, __ldg(wlv + k), lv);
        }
        float zz = mu + eps[b * Z + tid] * expf(0.5f * lv);
        out[b * Z + tid] = mu;
        out[B * Z + b * Z + tid] = lv;
        out[2 * B * Z + b * (H + Z) + H + tid] = zz;
    }
    out[2 * B * Z + b * (H + Z) + tid] = s_hb[tid];   // tid < 384 == H
}

// ---------------- launch ----------------
extern "C" void kernel_launch(void* const* d_in, const int* in_sizes, int n_in,
                              void* d_out, int out_size) {
    const int*   seq   = (const int*)d_in[0];
    const float* eps   = (const float*)d_in[1];
    const float* embed = (const float*)d_in[2];
    const float* Wih0  = (const float*)d_in[3];
    const float* Whh0  = (const float*)d_in[4];
    const float* Wih1  = (const float*)d_in[5];
    const float* Whh1  = (const float*)d_in[6];
    const float* W1    = (const float*)d_in[7];
    const float* b1    = (const float*)d_in[8];
    const float* Wmu   = (const float*)d_in[9];
    const float* bmu   = (const float*)d_in[10];
    const float* Wlv   = (const float*)d_in[11];
    const float* blv   = (const float*)d_in[12];
    float* out = (float*)d_out;

    static int smem_set = 0;
    const int dyn = 36864 + 73728 + 73728;   // 184320
    if (!smem_set) {
        cudaFuncSetAttribute(rnn_kernel, cudaFuncAttributeMaxDynamicSharedMemorySize, dyn);
        smem_set = 1;
    }

    act_kernel<<<1, 128>>>(seq);
    pre_kernel<<<dim3(12, 127), 256>>>(seq, embed, Wih0);
    rnn_kernel<<<128, 384, dyn>>>(Whh0, Wih1, Whh1, eps, W1, b1, Wmu, bmu, Wlv, blv, out);
}

// round 6
// speedup vs baseline: 3.7670x; 1.0996x over previous
#include <cuda_runtime.h>
#include <math.h>

#define B   128
#define T   128
#define E   512
#define H   384
#define FH  1536
#define Z   128
#define ZH  256
#define NSTEP 127

typedef unsigned long long ull;

// ---------------- device scratch ----------------
__device__ float g_G0[NSTEP * FH * B];     // precomputed x@Wih0^T, layout [t][j][b]
__device__ float g_h0[2][H * B];           // ping-pong, layout [feature][batch]
__device__ float g_h1[2][H * B];
__device__ int   g_act[NSTEP];
__device__ __align__(16) int g_slot[128];  // barrier arrival slots (monotonic epochs)
__device__ int   g_release;                // barrier release epoch (monotonic across replays)

// ---------------- helpers ----------------
__device__ __forceinline__ ull ffma2(ull a, ull b, ull c) {
    ull d; asm("fma.rn.f32x2 %0,%1,%2,%3;" : "=l"(d) : "l"(a), "l"(b), "l"(c)); return d;
}
__device__ __forceinline__ ull pack2(float x, float y) {
    ull r; asm("mov.b64 %0,{%1,%2};" : "=l"(r) : "f"(x), "f"(y)); return r;
}
__device__ __forceinline__ float sigf(float x) { return __fdividef(1.0f, 1.0f + __expf(-x)); }

// R3-proven grid barrier (DO NOT TOUCH): parallel slot arrivals + CTA0-warp
// aggregation + single release word + thread0 poll.
__device__ __forceinline__ void gsync(int epoch) {
    __threadfence();
    __syncthreads();
    if (threadIdx.x == 0) *((volatile int*)&g_slot[blockIdx.x]) = epoch;
    if (blockIdx.x == 0 && threadIdx.x < 32) {
        const volatile int* sp = g_slot;
        int i0 = threadIdx.x * 4;
        for (;;) {
            int a = sp[i0], b = sp[i0 + 1], c = sp[i0 + 2], d = sp[i0 + 3];
            bool ok = (a - epoch) >= 0 && (b - epoch) >= 0 && (c - epoch) >= 0 && (d - epoch) >= 0;
            if (__all_sync(0xffffffffu, ok)) break;
        }
        if (threadIdx.x == 0) *((volatile int*)&g_release) = epoch;
    }
    if (threadIdx.x == 0) { while ((*((volatile int*)&g_release) - epoch) < 0) {} }
    __syncthreads();
}

// ---------------- sticky active flags ----------------
__global__ void act_kernel(const int* __restrict__ seq) {
    __shared__ int nz[NSTEP];
    int t = threadIdx.x;
    if (t < NSTEP) {
        int s = 0;
        for (int b = 0; b < B; b++) s += seq[b * T + t + 1];
        nz[t] = (s != 0);
    }
    __syncthreads();
    if (t == 0) {
        int a = 1;
        for (int i = 0; i < NSTEP; i++) { a = a && nz[i]; g_act[i] = a; }
    }
}

// ---------------- precompute G0[t][j][b], 128x128 tile, f32x2 ----------------
__global__ __launch_bounds__(256) void pre_kernel(const int* __restrict__ seq,
                                                  const float* __restrict__ embed,
                                                  const float* __restrict__ Wih0) {
    const int t  = blockIdx.y;
    const int jb = blockIdx.x * 128;
    __shared__ int   s_idx[B];
    __shared__ float s_x[32 * 128];   // [k][b]
    __shared__ float s_w[32 * 128];   // [k][j]
    const int tid = threadIdx.x;
    if (tid < B) s_idx[tid] = seq[tid * T + t + 1];
    __syncthreads();

    const int col = tid & 127;
    const int kg  = tid >> 7;
    const int jt  = (tid >> 4) * 8;
    const int bt  = (tid & 15) * 8;

    ull acc[8][4];
#pragma unroll
    for (int u = 0; u < 8; u++)
#pragma unroll
        for (int v = 0; v < 4; v++) acc[u][v] = 0ull;

    const float* xrow0 = embed + (size_t)s_idx[col] * E;
    const float* wrow0 = Wih0 + (size_t)(jb + col) * E;

    for (int kc = 0; kc < E; kc += 32) {
#pragma unroll
        for (int q = 0; q < 4; q++) {
            float4 xv = __ldg((const float4*)(xrow0 + kc + kg * 16) + q);
            float4 wv = __ldg((const float4*)(wrow0 + kc + kg * 16) + q);
            int k0 = kg * 16 + q * 4;
            s_x[(k0 + 0) * 128 + col] = xv.x; s_x[(k0 + 1) * 128 + col] = xv.y;
            s_x[(k0 + 2) * 128 + col] = xv.z; s_x[(k0 + 3) * 128 + col] = xv.w;
            s_w[(k0 + 0) * 128 + col] = wv.x; s_w[(k0 + 1) * 128 + col] = wv.y;
            s_w[(k0 + 2) * 128 + col] = wv.z; s_w[(k0 + 3) * 128 + col] = wv.w;
        }
        __syncthreads();
#pragma unroll 4
        for (int k = 0; k < 32; k++) {
            const float4* xb = (const float4*)(s_x + k * 128 + bt);
            float4 x0 = xb[0], x1 = xb[1];
            ull xp0 = pack2(x0.x, x0.y), xp1 = pack2(x0.z, x0.w);
            ull xp2 = pack2(x1.x, x1.y), xp3 = pack2(x1.z, x1.w);
            const float4* wb = (const float4*)(s_w + k * 128 + jt);
            float4 w0 = wb[0], w1 = wb[1];
            float wf[8] = {w0.x, w0.y, w0.z, w0.w, w1.x, w1.y, w1.z, w1.w};
#pragma unroll
            for (int u = 0; u < 8; u++) {
                ull wp = pack2(wf[u], wf[u]);
                acc[u][0] = ffma2(xp0, wp, acc[u][0]);
                acc[u][1] = ffma2(xp1, wp, acc[u][1]);
                acc[u][2] = ffma2(xp2, wp, acc[u][2]);
                acc[u][3] = ffma2(xp3, wp, acc[u][3]);
            }
        }
        __syncthreads();
    }
#pragma unroll
    for (int u = 0; u < 8; u++) {
        ull* dst = (ull*)(g_G0 + ((size_t)t * FH + jb + jt + u) * B + bt);
        dst[0] = acc[u][0]; dst[1] = acc[u][1]; dst[2] = acc[u][2]; dst[3] = acc[u][3];
    }
}

// ---------------- persistent recurrent kernel + VAE head ----------------
// 128 CTAs x 384 threads. CTA bx owns 12 gate-rows {g*H + 3bx + hf}.
// Warps split K; h loads software-pipelined (prefetch next 4-k group).
extern __shared__ char dynsmem[];

__global__ __launch_bounds__(384, 1) void rnn_kernel(
    const float* __restrict__ Whh0, const float* __restrict__ Wih1,
    const float* __restrict__ Whh1, const float* __restrict__ eps,
    const float* __restrict__ W1,   const float* __restrict__ bias1,
    const float* __restrict__ Wmu,  const float* __restrict__ bmu,
    const float* __restrict__ Wlv,  const float* __restrict__ blv,
    float* __restrict__ out) {

    float2* sW0  = (float2*)dynsmem;                       // [384][12] dup pairs
    float2* sW1  = (float2*)(dynsmem + 36864);             // [768][12] dup pairs
    float*  sRed = (float*)(dynsmem + 36864 + 73728);      // [12 warps][12 rows][128 b]

    const int tid  = threadIdx.x;
    const int lane = tid & 31;
    const int w    = tid >> 5;
    const int bx   = blockIdx.x;

    // persistent weights, duplicated as (w,w) for f32x2
    for (int i = tid; i < 384 * 12; i += 384) {
        int k = i / 12, lr = i % 12;
        int g = lr / 3, hf = lr % 3;
        float v = Whh0[(g * H + bx * 3 + hf) * H + k];
        sW0[i] = make_float2(v, v);
    }
    for (int i = tid; i < 768 * 12; i += 384) {
        int k = i / 12, lr = i % 12;
        int g = lr / 3, hf = lr % 3;
        int j = g * H + bx * 3 + hf;
        float v = (k < 384) ? Wih1[j * H + k] : Whh1[j * H + (k - 384)];
        sW1[i] = make_float2(v, v);
    }
    // zero-init this CTA's h features
    {
        int idx = bx * 3 * B + tid;     // 384 = 3*B
        g_h0[0][idx] = 0.0f;
        g_h1[0][idx] = 0.0f;
    }
    // epilogue thread role + register cell state
    const int hf_e = tid >> 7;      // 0..2
    const int b_e  = tid & 127;
    const int rowb = bx * 3 + hf_e;
    float c0r = 0.0f, c1r = 0.0f;

    const int ebase = *((volatile int*)&g_release);   // replay-safe monotonic base
    int epoch = ebase;
    gsync(++epoch);

    int p = 0;
    int t;
    for (t = 0; t < NSTEP; t++) {
        if (!g_act[t]) break;
        const float* h0r = g_h0[p];
        float*       h0w = g_h0[p ^ 1];
        const float* h1r = g_h1[p];
        float*       h1w = g_h1[p ^ 1];

        // ---- G0[t] prefetch (DRAM; consumed in epilogue0, hidden under pass0)
        float g0p[4];
#pragma unroll
        for (int g = 0; g < 4; g++)
            g0p[g] = __ldcs(g_G0 + ((size_t)t * FH + g * H + rowb) * B + b_e);

        // ---- pass0 inner: rows x h0r, K=384 (32 k per warp), pipelined loads
        {
            ull acc[12][2];
#pragma unroll
            for (int r = 0; r < 12; r++) { acc[r][0] = 0ull; acc[r][1] = 0ull; }
            const int k0 = w * 32;
            float4 nb[4];
#pragma unroll
            for (int j = 0; j < 4; j++)
                nb[j] = __ldcg((const float4*)(h0r + (k0 + j) * B) + lane);
#pragma unroll
            for (int kk = 0; kk < 32; kk += 4) {
                float4 cb[4];
#pragma unroll
                for (int j = 0; j < 4; j++) cb[j] = nb[j];
                if (kk + 4 < 32) {
#pragma unroll
                    for (int j = 0; j < 4; j++)
                        nb[j] = __ldcg((const float4*)(h0r + (k0 + kk + 4 + j) * B) + lane);
                }
#pragma unroll
                for (int j = 0; j < 4; j++) {
                    int k = k0 + kk + j;
                    ull hlo = pack2(cb[j].x, cb[j].y), hhi = pack2(cb[j].z, cb[j].w);
                    const ulonglong2* wb = (const ulonglong2*)(sW0 + k * 12);
#pragma unroll
                    for (int q = 0; q < 6; q++) {
                        ulonglong2 ww = wb[q];
                        acc[2 * q][0]     = ffma2(hlo, ww.x, acc[2 * q][0]);
                        acc[2 * q][1]     = ffma2(hhi, ww.x, acc[2 * q][1]);
                        acc[2 * q + 1][0] = ffma2(hlo, ww.y, acc[2 * q + 1][0]);
                        acc[2 * q + 1][1] = ffma2(hhi, ww.y, acc[2 * q + 1][1]);
                    }
                }
            }
#pragma unroll
            for (int r = 0; r < 12; r++) {
                ulonglong2 v; v.x = acc[r][0]; v.y = acc[r][1];
                *(ulonglong2*)(sRed + (w * 12 + r) * B + 4 * lane) = v;
            }
        }
        __syncthreads();
        // ---- epilogue 0: gates0 = G0[t] + sum(partials)
        {
            float gv[4];
#pragma unroll
            for (int g = 0; g < 4; g++) {
                float s = g0p[g];
#pragma unroll
                for (int w2 = 0; w2 < 12; w2++) s += sRed[(w2 * 12 + g * 3 + hf_e) * B + b_e];
                gv[g] = s;
            }
            float nc = sigf(gv[1]) * c0r + sigf(gv[0]) * tanhf(gv[2]);
            c0r = nc;
            __stcg(h0w + rowb * B + b_e, sigf(gv[3]) * tanhf(nc));
        }
        gsync(++epoch);

        // ---- pass1: rows x [h0w | h1r], K=768 (64 k per warp), pipelined loads
        {
            ull acc[12][2];
#pragma unroll
            for (int r = 0; r < 12; r++) { acc[r][0] = 0ull; acc[r][1] = 0ull; }
            const float* src   = (w < 6) ? h0w : h1r;
            const int    fbase = (w < 6) ? w * 64 : (w - 6) * 64;
            const int    k0    = w * 64;
            float4 nb[4];
#pragma unroll
            for (int j = 0; j < 4; j++)
                nb[j] = __ldcg((const float4*)(src + (fbase + j) * B) + lane);
#pragma unroll
            for (int kk = 0; kk < 64; kk += 4) {
                float4 cb[4];
#pragma unroll
                for (int j = 0; j < 4; j++) cb[j] = nb[j];
                if (kk + 4 < 64) {
#pragma unroll
                    for (int j = 0; j < 4; j++)
                        nb[j] = __ldcg((const float4*)(src + (fbase + kk + 4 + j) * B) + lane);
                }
#pragma unroll
                for (int j = 0; j < 4; j++) {
                    ull hlo = pack2(cb[j].x, cb[j].y), hhi = pack2(cb[j].z, cb[j].w);
                    const ulonglong2* wb = (const ulonglong2*)(sW1 + (k0 + kk + j) * 12);
#pragma unroll
                    for (int q = 0; q < 6; q++) {
                        ulonglong2 ww = wb[q];
                        acc[2 * q][0]     = ffma2(hlo, ww.x, acc[2 * q][0]);
                        acc[2 * q][1]     = ffma2(hhi, ww.x, acc[2 * q][1]);
                        acc[2 * q + 1][0] = ffma2(hlo, ww.y, acc[2 * q + 1][0]);
                        acc[2 * q + 1][1] = ffma2(hhi, ww.y, acc[2 * q + 1][1]);
                    }
                }
            }
#pragma unroll
            for (int r = 0; r < 12; r++) {
                ulonglong2 v; v.x = acc[r][0]; v.y = acc[r][1];
                *(ulonglong2*)(sRed + (w * 12 + r) * B + 4 * lane) = v;
            }
        }
        __syncthreads();
        // ---- epilogue 1
        {
            float gv[4];
#pragma unroll
            for (int g = 0; g < 4; g++) {
                float s = 0.0f;
#pragma unroll
                for (int w2 = 0; w2 < 12; w2++) s += sRed[(w2 * 12 + g * 3 + hf_e) * B + b_e];
                gv[g] = s;
            }
            float nc = sigf(gv[1]) * c1r + sigf(gv[0]) * tanhf(gv[2]);
            c1r = nc;
            __stcg(h1w + rowb * B + b_e, sigf(gv[3]) * tanhf(nc));
        }
        __syncthreads();   // protect sRed before next step's partial stores
        p ^= 1;
    }

    // ---- FINAL grid barrier: head reads h1 features written by ALL CTAs.
    gsync(++epoch);

    // ---- VAE head: CTA bx handles batch row b = bx
    float* s_hb = sRed;            // reuse
    float* s_hv = sRed + 512;
    const float* h1f = g_h1[p];
    const int b = bx;
    s_hb[tid] = __ldcg(h1f + tid * B + b);   // tid < 384 == H
    __syncthreads();
    if (tid < ZH) {
        float a = bias1[tid];
        const float* wr = W1 + tid * H;
#pragma unroll 4
        for (int k = 0; k < H; k++) a = fmaf(s_hb[k], __ldg(wr + k), a);
        s_hv[tid] = fmaxf(a, 0.0f);
    }
    __syncthreads();
    if (tid < Z) {
        float mu = bmu[tid], lv = blv[tid];
        const float* wmu = Wmu + tid * ZH;
        const float* wlv = Wlv + tid * ZH;
#pragma unroll 4
        for (int k = 0; k < ZH; k++) {
            float hk = s_hv[k];
            mu = fmaf(hk, __ldg(wmu + k), mu);
            lv = fmaf(hk, __ldg(wlv + k), lv);
        }
        float zz = mu + eps[b * Z + tid] * expf(0.5f * lv);
        out[b * Z + tid] = mu;
        out[B * Z + b * Z + tid] = lv;
        out[2 * B * Z + b * (H + Z) + H + tid] = zz;
    }
    out[2 * B * Z + b * (H + Z) + tid] = s_hb[tid];   // tid < 384 == H
}

// ---------------- launch ----------------
extern "C" void kernel_launch(void* const* d_in, const int* in_sizes, int n_in,
                              void* d_out, int out_size) {
    const int*   seq   = (const int*)d_in[0];
    const float* eps   = (const float*)d_in[1];
    const float* embed = (const float*)d_in[2];
    const float* Wih0  = (const float*)d_in[3];
    const float* Whh0  = (const float*)d_in[4];
    const float* Wih1  = (const float*)d_in[5];
    const float* Whh1  = (const float*)d_in[6];
    const float* W1    = (const float*)d_in[7];
    const float* b1    = (const float*)d_in[8];
    const float* Wmu   = (const float*)d_in[9];
    const float* bmu   = (const float*)d_in[10];
    const float* Wlv   = (const float*)d_in[11];
    const float* blv   = (const float*)d_in[12];
    float* out = (float*)d_out;

    static int smem_set = 0;
    const int dyn = 36864 + 73728 + 73728;   // 184320
    if (!smem_set) {
        cudaFuncSetAttribute(rnn_kernel, cudaFuncAttributeMaxDynamicSharedMemorySize, dyn);
        smem_set = 1;
    }

    act_kernel<<<1, 128>>>(seq);
    pre_kernel<<<dim3(12, 127), 256>>>(seq, embed, Wih0);
    rnn_kernel<<<128, 384, dyn>>>(Whh0, Wih1, Whh1, eps, W1, b1, Wmu, bmu, Wlv, blv, out);
}

// round 7
// speedup vs baseline: 3.9416x; 1.0463x over previous
#include <cuda_runtime.h>
#include <math.h>

#define B   128
#define T   128
#define E   512
#define H   384
#define FH  1536
#define Z   128
#define ZH  256
#define NSTEP 127

typedef unsigned long long ull;

// ---------------- device scratch ----------------
__device__ float g_G0[NSTEP * FH * B];     // precomputed x@Wih0^T, layout [t][j][b]
__device__ float g_h0[2][H * B];           // ping-pong, layout [feature][batch]
__device__ float g_h1[2][H * B];
__device__ int   g_act[NSTEP];
__device__ __align__(16) int g_slot[128];  // barrier arrival slots (monotonic epochs)
__device__ int   g_release;                // barrier release epoch (monotonic across replays)

// ---------------- helpers ----------------
__device__ __forceinline__ ull ffma2(ull a, ull b, ull c) {
    ull d; asm("fma.rn.f32x2 %0,%1,%2,%3;" : "=l"(d) : "l"(a), "l"(b), "l"(c)); return d;
}
__device__ __forceinline__ ull pack2(float x, float y) {
    ull r; asm("mov.b64 %0,{%1,%2};" : "=l"(r) : "f"(x), "f"(y)); return r;
}
__device__ __forceinline__ float sigf(float x) { return __fdividef(1.0f, 1.0f + __expf(-x)); }

// R3-proven grid barrier (DO NOT TOUCH)
__device__ __forceinline__ void gsync(int epoch) {
    __threadfence();
    __syncthreads();
    if (threadIdx.x == 0) *((volatile int*)&g_slot[blockIdx.x]) = epoch;
    if (blockIdx.x == 0 && threadIdx.x < 32) {
        const volatile int* sp = g_slot;
        int i0 = threadIdx.x * 4;
        for (;;) {
            int a = sp[i0], b = sp[i0 + 1], c = sp[i0 + 2], d = sp[i0 + 3];
            bool ok = (a - epoch) >= 0 && (b - epoch) >= 0 && (c - epoch) >= 0 && (d - epoch) >= 0;
            if (__all_sync(0xffffffffu, ok)) break;
        }
        if (threadIdx.x == 0) *((volatile int*)&g_release) = epoch;
    }
    if (threadIdx.x == 0) { while ((*((volatile int*)&g_release) - epoch) < 0) {} }
    __syncthreads();
}

// ---------------- sticky active flags ----------------
__global__ void act_kernel(const int* __restrict__ seq) {
    __shared__ int nz[NSTEP];
    int t = threadIdx.x;
    if (t < NSTEP) {
        int s = 0;
#pragma unroll 8
        for (int b = 0; b < B; b++) s += seq[b * T + t + 1];
        nz[t] = (s != 0);
    }
    __syncthreads();
    if (t == 0) {
        int a = 1;
        for (int i = 0; i < NSTEP; i++) { a = a && nz[i]; g_act[i] = a; }
    }
}

// ---------------- precompute G0[t][j][b], 128x128 tile, f32x2 ----------------
__global__ __launch_bounds__(256) void pre_kernel(const int* __restrict__ seq,
                                                  const float* __restrict__ embed,
                                                  const float* __restrict__ Wih0) {
    const int t  = blockIdx.y;
    const int jb = blockIdx.x * 128;
    __shared__ int   s_idx[B];
    __shared__ float s_x[32 * 128];   // [k][b]
    __shared__ float s_w[32 * 128];   // [k][j]
    const int tid = threadIdx.x;
    if (tid < B) s_idx[tid] = seq[tid * T + t + 1];
    __syncthreads();

    const int col = tid & 127;
    const int kg  = tid >> 7;
    const int jt  = (tid >> 4) * 8;
    const int bt  = (tid & 15) * 8;

    ull acc[8][4];
#pragma unroll
    for (int u = 0; u < 8; u++)
#pragma unroll
        for (int v = 0; v < 4; v++) acc[u][v] = 0ull;

    const float* xrow0 = embed + (size_t)s_idx[col] * E;
    const float* wrow0 = Wih0 + (size_t)(jb + col) * E;

    for (int kc = 0; kc < E; kc += 32) {
#pragma unroll
        for (int q = 0; q < 4; q++) {
            float4 xv = __ldg((const float4*)(xrow0 + kc + kg * 16) + q);
            float4 wv = __ldg((const float4*)(wrow0 + kc + kg * 16) + q);
            int k0 = kg * 16 + q * 4;
            s_x[(k0 + 0) * 128 + col] = xv.x; s_x[(k0 + 1) * 128 + col] = xv.y;
            s_x[(k0 + 2) * 128 + col] = xv.z; s_x[(k0 + 3) * 128 + col] = xv.w;
            s_w[(k0 + 0) * 128 + col] = wv.x; s_w[(k0 + 1) * 128 + col] = wv.y;
            s_w[(k0 + 2) * 128 + col] = wv.z; s_w[(k0 + 3) * 128 + col] = wv.w;
        }
        __syncthreads();
#pragma unroll 4
        for (int k = 0; k < 32; k++) {
            const float4* xb = (const float4*)(s_x + k * 128 + bt);
            float4 x0 = xb[0], x1 = xb[1];
            ull xp0 = pack2(x0.x, x0.y), xp1 = pack2(x0.z, x0.w);
            ull xp2 = pack2(x1.x, x1.y), xp3 = pack2(x1.z, x1.w);
            const float4* wb = (const float4*)(s_w + k * 128 + jt);
            float4 w0 = wb[0], w1 = wb[1];
            float wf[8] = {w0.x, w0.y, w0.z, w0.w, w1.x, w1.y, w1.z, w1.w};
#pragma unroll
            for (int u = 0; u < 8; u++) {
                ull wp = pack2(wf[u], wf[u]);
                acc[u][0] = ffma2(xp0, wp, acc[u][0]);
                acc[u][1] = ffma2(xp1, wp, acc[u][1]);
                acc[u][2] = ffma2(xp2, wp, acc[u][2]);
                acc[u][3] = ffma2(xp3, wp, acc[u][3]);
            }
        }
        __syncthreads();
    }
#pragma unroll
    for (int u = 0; u < 8; u++) {
        ull* dst = (ull*)(g_G0 + ((size_t)t * FH + jb + jt + u) * B + bt);
        dst[0] = acc[u][0]; dst[1] = acc[u][1]; dst[2] = acc[u][2]; dst[3] = acc[u][3];
    }
}

// ---------------- persistent recurrent kernel + VAE head ----------------
// 2D tiling: 128 CTAs = 64 row-groups x 2 batch-groups.
// CTA owns 24 gate-rows {g*H + RG*6 + f, f=0..5} x 64 batches [BG*64, BG*64+64).
// 12 warps split K. Weights stored as ROW-PAIRS (f32x2, no dup); h duplicated per lane.
extern __shared__ char dynsmem[];

__global__ __launch_bounds__(384, 1) void rnn_kernel(
    const float* __restrict__ Whh0, const float* __restrict__ Wih1,
    const float* __restrict__ Whh1, const float* __restrict__ eps,
    const float* __restrict__ W1,   const float* __restrict__ bias1,
    const float* __restrict__ Wmu,  const float* __restrict__ bmu,
    const float* __restrict__ Wlv,  const float* __restrict__ blv,
    float* __restrict__ out) {

    float2* sW0p = (float2*)dynsmem;                       // [384][12] row-pairs (36864 B)
    float2* sW1p = (float2*)(dynsmem + 36864);             // [768][12] row-pairs (73728 B)
    float*  sRedP = (float*)(dynsmem + 36864 + 73728);     // [12 w][12 rp][128]  (73728 B)

    const int tid  = threadIdx.x;
    const int lane = tid & 31;
    const int w    = tid >> 5;
    const int bx   = blockIdx.x;
    const int RG   = bx >> 1;         // row-group 0..63
    const int BOFF = (bx & 1) * 64;   // batch offset

    // persistent weights: pair rows (j0, j0+1) into float2
    for (int i = tid; i < 384 * 12; i += 384) {
        int k = i / 12, rp = i % 12;
        int g = rp / 3, fp = rp % 3;
        int j0 = g * H + RG * 6 + fp * 2;
        sW0p[i] = make_float2(Whh0[j0 * H + k], Whh0[(j0 + 1) * H + k]);
    }
    for (int i = tid; i < 768 * 12; i += 384) {
        int k = i / 12, rp = i % 12;
        int g = rp / 3, fp = rp % 3;
        int j0 = g * H + RG * 6 + fp * 2;
        float a, bv;
        if (k < 384) { a = Wih1[j0 * H + k];        bv = Wih1[(j0 + 1) * H + k]; }
        else         { a = Whh1[j0 * H + k - 384];  bv = Whh1[(j0 + 1) * H + k - 384]; }
        sW1p[i] = make_float2(a, bv);
    }
    // epilogue role: thread = (f, bl); zero-init this CTA's (f,b) elements
    const int f_e  = tid >> 6;        // 0..5
    const int bl_e = tid & 63;        // 0..63
    const int hrow = RG * 6 + f_e;    // h feature index
    {
        int idx = hrow * B + BOFF + bl_e;
        g_h0[0][idx] = 0.0f;
        g_h1[0][idx] = 0.0f;
    }
    float c0r = 0.0f, c1r = 0.0f;

    const int ebase = *((volatile int*)&g_release);
    int epoch = ebase;
    gsync(++epoch);

    int p = 0;
    int t;
    for (t = 0; t < NSTEP; t++) {
        if (!g_act[t]) break;
        const float* h0r = g_h0[p];
        float*       h0w = g_h0[p ^ 1];
        const float* h1r = g_h1[p];
        float*       h1w = g_h1[p ^ 1];

        // ---- G0[t] prefetch (consumed in epilogue0)
        float g0p[4];
#pragma unroll
        for (int g = 0; g < 4; g++)
            g0p[g] = __ldcs(g_G0 + ((size_t)t * FH + g * H + hrow) * B + BOFF + bl_e);

        // ---- pass0: 24 rows x h0r[:, BOFF..BOFF+64), K=384 (32 k/warp), pipelined
        {
            ull acc[12][2];
#pragma unroll
            for (int r = 0; r < 12; r++) { acc[r][0] = 0ull; acc[r][1] = 0ull; }
            const int k0 = w * 32;
            float2 nb[4];
#pragma unroll
            for (int j = 0; j < 4; j++)
                nb[j] = __ldcg((const float2*)(h0r + (k0 + j) * B + BOFF) + lane);
#pragma unroll
            for (int kk = 0; kk < 32; kk += 4) {
                float2 cb[4];
#pragma unroll
                for (int j = 0; j < 4; j++) cb[j] = nb[j];
                if (kk + 4 < 32) {
#pragma unroll
                    for (int j = 0; j < 4; j++)
                        nb[j] = __ldcg((const float2*)(h0r + (k0 + kk + 4 + j) * B + BOFF) + lane);
                }
#pragma unroll
                for (int j = 0; j < 4; j++) {
                    ull hd0 = pack2(cb[j].x, cb[j].x);
                    ull hd1 = pack2(cb[j].y, cb[j].y);
                    const ulonglong2* wb = (const ulonglong2*)(sW0p + (k0 + kk + j) * 12);
#pragma unroll
                    for (int q = 0; q < 6; q++) {
                        ulonglong2 ww = wb[q];
                        acc[2 * q][0]     = ffma2(hd0, ww.x, acc[2 * q][0]);
                        acc[2 * q][1]     = ffma2(hd1, ww.x, acc[2 * q][1]);
                        acc[2 * q + 1][0] = ffma2(hd0, ww.y, acc[2 * q + 1][0]);
                        acc[2 * q + 1][1] = ffma2(hd1, ww.y, acc[2 * q + 1][1]);
                    }
                }
            }
#pragma unroll
            for (int r = 0; r < 12; r++) {
                ulonglong2 v; v.x = acc[r][0]; v.y = acc[r][1];
                *(ulonglong2*)(sRedP + (w * 12 + r) * 128 + 4 * lane) = v;
            }
        }
        __syncthreads();
        // ---- epilogue 0: gates0 = G0[t] + sum(partials); idx = 2*bl + rowinpair
        {
            const int rpo = (f_e >> 1);
            const int ri  = (f_e & 1);
            const int sidx = 2 * bl_e + ri;
            float gv[4];
#pragma unroll
            for (int g = 0; g < 4; g++) {
                float s = g0p[g];
                int base = (g * 3 + rpo) * 128 + sidx;
#pragma unroll
                for (int w2 = 0; w2 < 12; w2++) s += sRedP[w2 * 12 * 128 + base];
                gv[g] = s;
            }
            float nc = sigf(gv[1]) * c0r + sigf(gv[0]) * tanhf(gv[2]);
            c0r = nc;
            __stcg(h0w + hrow * B + BOFF + bl_e, sigf(gv[3]) * tanhf(nc));
        }
        gsync(++epoch);

        // ---- pass1: 24 rows x [h0w | h1r], K=768 (64 k/warp), pipelined
        {
            ull acc[12][2];
#pragma unroll
            for (int r = 0; r < 12; r++) { acc[r][0] = 0ull; acc[r][1] = 0ull; }
            const float* src   = (w < 6) ? h0w : h1r;
            const int    fbase = (w < 6) ? w * 64 : (w - 6) * 64;
            const int    k0    = w * 64;
            float2 nb[4];
#pragma unroll
            for (int j = 0; j < 4; j++)
                nb[j] = __ldcg((const float2*)(src + (fbase + j) * B + BOFF) + lane);
#pragma unroll
            for (int kk = 0; kk < 64; kk += 4) {
                float2 cb[4];
#pragma unroll
                for (int j = 0; j < 4; j++) cb[j] = nb[j];
                if (kk + 4 < 64) {
#pragma unroll
                    for (int j = 0; j < 4; j++)
                        nb[j] = __ldcg((const float2*)(src + (fbase + kk + 4 + j) * B + BOFF) + lane);
                }
#pragma unroll
                for (int j = 0; j < 4; j++) {
                    ull hd0 = pack2(cb[j].x, cb[j].x);
                    ull hd1 = pack2(cb[j].y, cb[j].y);
                    const ulonglong2* wb = (const ulonglong2*)(sW1p + (k0 + kk + j) * 12);
#pragma unroll
                    for (int q = 0; q < 6; q++) {
                        ulonglong2 ww = wb[q];
                        acc[2 * q][0]     = ffma2(hd0, ww.x, acc[2 * q][0]);
                        acc[2 * q][1]     = ffma2(hd1, ww.x, acc[2 * q][1]);
                        acc[2 * q + 1][0] = ffma2(hd0, ww.y, acc[2 * q + 1][0]);
                        acc[2 * q + 1][1] = ffma2(hd1, ww.y, acc[2 * q + 1][1]);
                    }
                }
            }
#pragma unroll
            for (int r = 0; r < 12; r++) {
                ulonglong2 v; v.x = acc[r][0]; v.y = acc[r][1];
                *(ulonglong2*)(sRedP + (w * 12 + r) * 128 + 4 * lane) = v;
            }
        }
        __syncthreads();
        // ---- epilogue 1
        {
            const int rpo = (f_e >> 1);
            const int ri  = (f_e & 1);
            const int sidx = 2 * bl_e + ri;
            float gv[4];
#pragma unroll
            for (int g = 0; g < 4; g++) {
                float s = 0.0f;
                int base = (g * 3 + rpo) * 128 + sidx;
#pragma unroll
                for (int w2 = 0; w2 < 12; w2++) s += sRedP[w2 * 12 * 128 + base];
                gv[g] = s;
            }
            float nc = sigf(gv[1]) * c1r + sigf(gv[0]) * tanhf(gv[2]);
            c1r = nc;
            __stcg(h1w + hrow * B + BOFF + bl_e, sigf(gv[3]) * tanhf(nc));
        }
        __syncthreads();   // protect sRedP before next step's stores
        p ^= 1;
    }

    // ---- FINAL grid barrier: head reads h1 features written by ALL CTAs.
    gsync(++epoch);

    // ---- VAE head: CTA bx handles batch row b = bx
    float* s_hb = sRedP;
    float* s_hv = sRedP + 512;
    const float* h1f = g_h1[p];
    const int b = bx;
    s_hb[tid] = __ldcg(h1f + tid * B + b);   // tid < 384 == H
    __syncthreads();
    if (tid < ZH) {
        float a = bias1[tid];
        const float* wr = W1 + tid * H;
#pragma unroll 4
        for (int k = 0; k < H; k++) a = fmaf(s_hb[k], __ldg(wr + k), a);
        s_hv[tid] = fmaxf(a, 0.0f);
    }
    __syncthreads();
    if (tid < Z) {
        float mu = bmu[tid], lv = blv[tid];
        const float* wmu = Wmu + tid * ZH;
        const float* wlv = Wlv + tid * ZH;
#pragma unroll 4
        for (int k = 0; k < ZH; k++) {
            float hk = s_hv[k];
            mu = fmaf(hk, __ldg(wmu + k), mu);
            lv = fmaf(hk, __ldg(wlv + k), lv);
        }
        float zz = mu + eps[b * Z + tid] * expf(0.5f * lv);
        out[b * Z + tid] = mu;
        out[B * Z + b * Z + tid] = lv;
        out[2 * B * Z + b * (H + Z) + H + tid] = zz;
    }
    out[2 * B * Z + b * (H + Z) + tid] = s_hb[tid];   // tid < 384 == H
}

// ---------------- launch ----------------
extern "C" void kernel_launch(void* const* d_in, const int* in_sizes, int n_in,
                              void* d_out, int out_size) {
    const int*   seq   = (const int*)d_in[0];
    const float* eps   = (const float*)d_in[1];
    const float* embed = (const float*)d_in[2];
    const float* Wih0  = (const float*)d_in[3];
    const float* Whh0  = (const float*)d_in[4];
    const float* Wih1  = (const float*)d_in[5];
    const float* Whh1  = (const float*)d_in[6];
    const float* W1    = (const float*)d_in[7];
    const float* b1    = (const float*)d_in[8];
    const float* Wmu   = (const float*)d_in[9];
    const float* bmu   = (const float*)d_in[10];
    const float* Wlv   = (const float*)d_in[11];
    const float* blv   = (const float*)d_in[12];
    float* out = (float*)d_out;

    static int smem_set = 0;
    const int dyn = 36864 + 73728 + 73728;   // 184320
    if (!smem_set) {
        cudaFuncSetAttribute(rnn_kernel, cudaFuncAttributeMaxDynamicSharedMemorySize, dyn);
        smem_set = 1;
    }

    act_kernel<<<1, 128>>>(seq);
    pre_kernel<<<dim3(12, 127), 256>>>(seq, embed, Wih0);
    rnn_kernel<<<128, 384, dyn>>>(Whh0, Wih1, Whh1, eps, W1, b1, Wmu, bmu, Wlv, blv, out);
}